// round 16
// baseline (speedup 1.0000x reference)
#include <cuda_runtime.h>
#include <cstdint>

// field[i,j] = sum_n w_n * ox_n[i] * oy_n[j] / (lx*ly)
// dims < 3/G per axis -> footprint <= 4x4 cells.
// R15: SINGLE fused kernel. 592 CTAs (148 SMs x 4, provably co-resident via
//      __launch_bounds__(256,4)): zero own slice -> release-arrive on a
//      monotonic __device__ epoch counter -> prefetch iter-0 rect inputs
//      (overlaps the spin) -> acquire-spin until all 592 arrived -> quad v4
//      REDs for iter-0 and the grid-stride iter-1.
// Counter is monotonic (never reset) so graph replays are self-consistent.

#define G 256
#define TPB 256
#define NCTA 592          // 148 * 4, all wave-1 resident

__device__ unsigned long long g_epoch_ctr = 0ULL;

__device__ __forceinline__ void red_v4(float* addr, float v0, float v1, float v2, float v3) {
    asm volatile("red.global.add.v4.f32 [%0], {%1, %2, %3, %4};"
                 :: "l"(addr), "f"(v0), "f"(v1), "f"(v2), "f"(v3) : "memory");
}

// Scatter one rect given raw inputs + precomputed grid constants.
__device__ __forceinline__ void scatter_rect(
    float2 p, float2 d, float w, float4 b,
    float inv_lx, float inv_ly, float* __restrict__ field)
{
    const float x0u = (p.x - b.x) * inv_lx;
    const float x1u = (p.x + d.x - b.x) * inv_lx;
    const float y0u = (p.y - b.y) * inv_ly;
    const float y1u = (p.y + d.y - b.y) * inv_ly;

    const int i0 = max((int)floorf(x0u), 0);
    const int j0 = max((int)floorf(y0u), 0);
    const int jq0 = j0 & ~3;              // aligned quad base, <= 252: in-grid
    const int jq1 = jq0 + 4;

    float q0[4], q1[4];
    #pragma unroll
    for (int k = 0; k < 4; k++) {
        float c = (float)(jq0 + k);
        q0[k] = fmaxf(fminf(y1u, c + 1.0f) - fmaxf(y0u, c), 0.0f);
    }
    const bool use1 = (jq1 < G) && (y1u > (float)jq1);
    #pragma unroll
    for (int k = 0; k < 4; k++) {
        float c = (float)(jq1 + k);
        q1[k] = fmaxf(fminf(y1u, c + 1.0f) - fmaxf(y0u, c), 0.0f);
    }

    #pragma unroll
    for (int s = 0; s < 4; s++) {
        int i = i0 + s;
        float fi = (float)i;
        float oxu = fmaxf(fminf(x1u, fi + 1.0f) - fmaxf(x0u, fi), 0.0f);
        float sx = w * oxu;
        if (i < G && sx != 0.0f) {
            float* rowbase = field + i * G;
            red_v4(rowbase + jq0, sx * q0[0], sx * q0[1], sx * q0[2], sx * q0[3]);
            if (use1) red_v4(rowbase + jq1, sx * q1[0], sx * q1[1], sx * q1[2], sx * q1[3]);
        }
    }
}

__global__ void __launch_bounds__(TPB, 4) charge_fused_kernel(
    const float4* __restrict__ boundary,  // [xmin, ymin, xmax, ymax]
    const float2* __restrict__ xy,        // [N]
    const float2* __restrict__ dims,      // [N]
    const float* __restrict__ cw,         // [N]
    float* __restrict__ field,            // [G*G]
    int n, int nf4)
{
    const int tid = threadIdx.x;
    const int bid = blockIdx.x;

    // ---- Zero this CTA's slice of field (first 64 CTAs do all of it) ----
    {
        int zidx = bid * TPB + tid;
        if (zidx < nf4)
            reinterpret_cast<float4*>(field)[zidx] = make_float4(0.f, 0.f, 0.f, 0.f);
    }
    __syncthreads();   // all slice stores done before this CTA's arrive

    // ---- Release-arrive on the monotonic epoch counter ----
    unsigned long long target = 0;
    if (tid == 0) {
        unsigned long long ticket;
        asm volatile("atom.add.release.gpu.u64 %0, [%1], 1;"
                     : "=l"(ticket) : "l"(&g_epoch_ctr) : "memory");
        target = (ticket / NCTA + 1ULL) * (unsigned long long)NCTA;
    }

    // ---- Prefetch iter-0 inputs (overlaps the spin below) ----
    const int r0 = bid * TPB + tid;
    const bool a0 = (r0 < n);
    const int rs = a0 ? r0 : 0;
    const float2 p0 = xy[rs];
    const float2 d0 = dims[rs];
    const float  w0 = cw[rs];
    const float4 b  = *boundary;
    const float inv_lx = __frcp_rn((b.z - b.x) * (1.0f / G));  // exact: lx = 2^-8
    const float inv_ly = __frcp_rn((b.w - b.y) * (1.0f / G));

    // ---- Acquire-spin until all NCTA CTAs have zeroed + arrived ----
    if (tid == 0) {
        unsigned long long v;
        do {
            asm volatile("ld.acquire.gpu.u64 %0, [%1];"
                         : "=l"(v) : "l"(&g_epoch_ctr) : "memory");
        } while (v < target);
    }
    __syncthreads();   // block waits on tid0's acquire

    // ---- Scatter iter-0 ----
    if (a0) scatter_rect(p0, d0, w0, b, inv_lx, inv_ly, field);

    // ---- Scatter iter-1 (grid-stride tail) ----
    const int r1 = r0 + NCTA * TPB;
    if (r1 < n) {
        float2 p1 = xy[r1];
        float2 d1 = dims[r1];
        float  w1 = cw[r1];
        scatter_rect(p1, d1, w1, b, inv_lx, inv_ly, field);
    }
}

extern "C" void kernel_launch(void* const* d_in, const int* in_sizes, int n_in,
                              void* d_out, int out_size) {
    const float4* boundary = (const float4*)d_in[0];
    const float2* xy       = (const float2*)d_in[1];
    const float2* dims     = (const float2*)d_in[2];
    const float*  cw       = (const float*)d_in[3];
    float* field = (float*)d_out;

    const int n = in_sizes[3];          // N_RECTS
    const int nf4 = out_size / 4;       // float4 count of field

    charge_fused_kernel<<<NCTA, TPB>>>(boundary, xy, dims, cw, field, n, nf4);
}

// round 17
// speedup vs baseline: 1.0257x; 1.0257x over previous
#include <cuda_runtime.h>
#include <cstdint>

// field[i,j] = sum_n w_n * ox_n[i] * oy_n[j] / (lx*ly)
// dims < 3/G per axis -> footprint <= 4x4 cells.
// R16: R9 structure (best measured) + perfectly balanced grid:
//      exactly 740 CTAs = 148 SMs x 5 -> 5.00 waves (was 782 -> 5.28 ragged).
//      Each thread loops over rects with stride NCTA*TPB (1-2 iterations).
// 1 rect per thread-iteration; cell-unit coords; aligned-quad
// red.global.add.v4.f32 (fire-and-forget).

#define G 256
#define TPB 256
#define NCTA 740           // 148 * 5 -> exact 5-wave balance

__global__ void zero_field_kernel4(float4* __restrict__ out, int n4) {
    int i = blockIdx.x * blockDim.x + threadIdx.x;
    if (i < n4) out[i] = make_float4(0.f, 0.f, 0.f, 0.f);
}

__device__ __forceinline__ void red_v4(float* addr, float v0, float v1, float v2, float v3) {
    asm volatile("red.global.add.v4.f32 [%0], {%1, %2, %3, %4};"
                 :: "l"(addr), "f"(v0), "f"(v1), "f"(v2), "f"(v3) : "memory");
}

__device__ __forceinline__ void scatter_rect(
    float2 p, float2 d, float w, float4 b,
    float inv_lx, float inv_ly, float* __restrict__ field)
{
    const float x0u = (p.x - b.x) * inv_lx;
    const float x1u = (p.x + d.x - b.x) * inv_lx;
    const float y0u = (p.y - b.y) * inv_ly;
    const float y1u = (p.y + d.y - b.y) * inv_ly;

    const int i0 = max((int)floorf(x0u), 0);
    const int j0 = max((int)floorf(y0u), 0);
    const int jq0 = j0 & ~3;              // aligned quad base, <= 252: in-grid
    const int jq1 = jq0 + 4;

    float q0[4], q1[4];
    #pragma unroll
    for (int k = 0; k < 4; k++) {
        float c = (float)(jq0 + k);
        q0[k] = fmaxf(fminf(y1u, c + 1.0f) - fmaxf(y0u, c), 0.0f);
    }
    const bool use1 = (jq1 < G) && (y1u > (float)jq1);
    #pragma unroll
    for (int k = 0; k < 4; k++) {
        float c = (float)(jq1 + k);
        q1[k] = fmaxf(fminf(y1u, c + 1.0f) - fmaxf(y0u, c), 0.0f);
    }

    #pragma unroll
    for (int s = 0; s < 4; s++) {
        int i = i0 + s;
        float fi = (float)i;
        float oxu = fmaxf(fminf(x1u, fi + 1.0f) - fmaxf(x0u, fi), 0.0f);
        float sx = w * oxu;
        if (i < G && sx != 0.0f) {
            float* rowbase = field + i * G;
            red_v4(rowbase + jq0, sx * q0[0], sx * q0[1], sx * q0[2], sx * q0[3]);
            if (use1) red_v4(rowbase + jq1, sx * q1[0], sx * q1[1], sx * q1[2], sx * q1[3]);
        }
    }
}

__global__ void __launch_bounds__(TPB) charge_scatter_kernel(
    const float4* __restrict__ boundary,  // [xmin, ymin, xmax, ymax]
    const float2* __restrict__ xy,        // [N]
    const float2* __restrict__ dims,      // [N]
    const float* __restrict__ cw,         // [N]
    float* __restrict__ field,            // [G*G]
    int n)
{
    const float4 b = *boundary;
    const float inv_lx = __frcp_rn((b.z - b.x) * (1.0f / G));  // exact: lx = 2^-8
    const float inv_ly = __frcp_rn((b.w - b.y) * (1.0f / G));

    const int stride = NCTA * TPB;        // 189,440
    for (int r = blockIdx.x * TPB + threadIdx.x; r < n; r += stride) {
        float2 p = xy[r];
        float2 d = dims[r];
        float  w = cw[r];
        scatter_rect(p, d, w, b, inv_lx, inv_ly, field);
    }
}

extern "C" void kernel_launch(void* const* d_in, const int* in_sizes, int n_in,
                              void* d_out, int out_size) {
    const float4* boundary = (const float4*)d_in[0];
    const float2* xy       = (const float2*)d_in[1];
    const float2* dims     = (const float2*)d_in[2];
    const float*  cw       = (const float*)d_in[3];
    float* field = (float*)d_out;

    const int n = in_sizes[3];          // N_RECTS

    int n4 = out_size / 4;              // 16384 float4s
    zero_field_kernel4<<<(n4 + 255) / 256, 256>>>((float4*)field, n4);

    charge_scatter_kernel<<<NCTA, TPB>>>(boundary, xy, dims, cw, field, n);
}